// round 10
// baseline (speedup 1.0000x reference)
#include <cuda_runtime.h>
#include <cuda_fp16.h>
#include <cstdint>

#define NUM_HEADS   8
#define HIDDEN_DIM  64
#define N_REAL      30000
#define N_VIRT      2000
#define N_NODES     (N_REAL + N_VIRT)
#define N_EDGES     512000
#define VEC_PER_ROW (HIDDEN_DIM / 4)   // 16 float4 (or uint2-of-half4) per node row
#define TB 256
#define N_REP 4                        // h2 replicas to de-contend REDG

// fused-kernel block ranges
#define PREP_INDEG_BLOCKS  (N_EDGES / TB)                  // 2000
#define PREP_H0_BLOCKS     (N_NODES * VEC_PER_ROW / TB)    // 2000
#define PREP_ZERO1_BLOCKS  (N_NODES * VEC_PER_ROW / TB)    // 2000
#define PREP_VPAIR_BLOCKS  (N_EDGES / TB)                  // 2000
#define PREP_ZERO2_BLOCKS  (N_VIRT * VEC_PER_ROW * N_REP / TB) // 500
#define E_PER 4
#define R1_BLOCKS          (N_EDGES / E_PER * VEC_PER_ROW / TB) // 8000
#define R2_BLOCKS          2048
#define BCAST_THREADS      (N_VIRT * NUM_HEADS * VEC_PER_ROW)   // 256000

// ---- device scratch (allocation-free) --------------------------------------
struct Zeroed {                         // zeroed with ONE memsetAsync
    int indeg[N_NODES];
    int vcnt;
    unsigned char needed[N_NODES];
};
__device__ Zeroed  g_z;
__device__ __half2 g_h0h[N_NODES * 32];            // f16 node features, 4 MB
__device__ float4  g_h1[N_NODES * VEC_PER_ROW];    // round-1 raw sums, 8 MB
__device__ float4  g_h2[N_REP][N_VIRT * VEC_PER_ROW]; // round-2 replicas, 2 MB
__device__ int     g_vsrc[N_EDGES];                // virtual-dst edge src ids
__device__ int     g_vdst[N_EDGES];                // matching virtual dst (0..N_VIRT-1)

__device__ __forceinline__ void red_add_v4(float4* addr, float4 v) {
    asm volatile("red.global.add.v4.f32 [%0], {%1,%2,%3,%4};"
                 :: "l"(addr), "f"(v.x), "f"(v.y), "f"(v.z), "f"(v.w)
                 : "memory");
}
__device__ __forceinline__ float winv_of(int node) {
    float di = (float)g_z.indeg[node];
    return di > 0.f ? __frcp_rn(di) : 0.f;
}

// ---------------------------------------------------------------------------
// K_prep (fused, block-range dispatch):
//   A: in-degree histogram     B: build f16 h0     C: zero h1
//   D: append (src, dst-N_REAL) pairs for virtual-dst edges + mark needed[src]
//   E: zero h2 replicas
__global__ void k_prep(const float4* __restrict__ features,
                       const float4* __restrict__ virtue_emb,
                       const int* __restrict__ cnodes,
                       const int* __restrict__ src,
                       const int* __restrict__ dst) {
    int b = blockIdx.x;
    if (b < PREP_INDEG_BLOCKS) {
        int e = b * TB + threadIdx.x;
        atomicAdd(&g_z.indeg[dst[e]], 1);
        return;
    }
    b -= PREP_INDEG_BLOCKS;
    if (b < PREP_H0_BLOCKS) {
        int t = b * TB + threadIdx.x;
        int v = t >> 4;
        int c = t & 15;
        float4 x;
        if (v < N_REAL) {
            int w = cnodes[v];
            x = features[(size_t)w * VEC_PER_ROW + c];
        } else {
            x = virtue_emb[(size_t)(v - N_REAL) * VEC_PER_ROW + c];
        }
        g_h0h[t * 2]     = __floats2half2_rn(x.x, x.y);
        g_h0h[t * 2 + 1] = __floats2half2_rn(x.z, x.w);
        return;
    }
    b -= PREP_H0_BLOCKS;
    if (b < PREP_ZERO1_BLOCKS) {
        int t = b * TB + threadIdx.x;
        g_h1[t] = make_float4(0.f, 0.f, 0.f, 0.f);
        return;
    }
    b -= PREP_ZERO1_BLOCKS;
    if (b < PREP_VPAIR_BLOCKS) {
        int e = b * TB + threadIdx.x;
        int dd = dst[e];
        if (dd < N_REAL) return;
        int s = src[e];
        int pos = atomicAdd(&g_z.vcnt, 1);
        g_vsrc[pos] = s;
        g_vdst[pos] = dd - N_REAL;
        g_z.needed[s] = 1;               // benign race
        return;
    }
    b -= PREP_VPAIR_BLOCKS;
    {
        int t = b * TB + threadIdx.x;
        ((float4*)g_h2)[t] = make_float4(0.f, 0.f, 0.f, 0.f);
    }
}

// K_round1: h1raw[d] += h0f16[s] for edges whose dst is needed.
// 16 lanes per edge, 4 edges per thread, loads batched for MLP.
__global__ void k_round1(const int* __restrict__ src,
                         const int* __restrict__ dst) {
    int t = blockIdx.x * TB + threadIdx.x;
    int c  = t & 15;
    int e0 = (t >> 4) * E_PER;

    int s[E_PER], d[E_PER];
#pragma unroll
    for (int j = 0; j < E_PER; j++) { s[j] = src[e0 + j]; d[j] = dst[e0 + j]; }
    unsigned char f[E_PER];
#pragma unroll
    for (int j = 0; j < E_PER; j++) f[j] = g_z.needed[d[j]];

    const uint2* h0 = reinterpret_cast<const uint2*>(g_h0h);
    uint2 q[E_PER];
#pragma unroll
    for (int j = 0; j < E_PER; j++)
        if (f[j]) q[j] = h0[s[j] * VEC_PER_ROW + c];
#pragma unroll
    for (int j = 0; j < E_PER; j++) {
        if (!f[j]) continue;
        __half2 a = *reinterpret_cast<__half2*>(&q[j].x);
        __half2 bb = *reinterpret_cast<__half2*>(&q[j].y);
        float2 fa = __half22float2(a);
        float2 fb = __half22float2(bb);
        red_add_v4(&g_h1[d[j] * VEC_PER_ROW + c],
                   make_float4(fa.x, fa.y, fb.x, fb.y));
    }
}

// K_round2e: edge-parallel round 2 over appended (src, vdst) pairs.
// x = h1raw[s] * winv[s]; reduce into one of 4 h2 replicas.
__global__ void k_round2e() {
    int nv = g_z.vcnt;
    int total = nv * VEC_PER_ROW;
    int rep = (threadIdx.x >> 5) & (N_REP - 1);
    for (int t = blockIdx.x * blockDim.x + threadIdx.x; t < total;
         t += gridDim.x * blockDim.x) {
        int e = t >> 4;
        int c = t & 15;
        int s = g_vsrc[e];
        int r = g_vdst[e];
        float w = winv_of(s);
        float4 x = g_h1[s * VEC_PER_ROW + c];
        x.x *= w; x.y *= w; x.z *= w; x.w *= w;
        red_add_v4(&g_h2[rep][r * VEC_PER_ROW + c], x);
    }
}

// K_bcast: one thread per OUTPUT float4 (2000*8*16 = 256K threads).
// Sums the 4 replicas (L2-broadcast reads), scales by winv[dst], one
// coalesced 16B store each. 1000 blocks — latency fully hidden.
__global__ void k_bcast(const int* __restrict__ vm_idx,
                        float4* __restrict__ out) {
    int t = blockIdx.x * blockDim.x + threadIdx.x;
    if (t >= BCAST_THREADS) return;
    int c = t & 15;
    int u = t >> 7;                         // (u, h, c) with h implicit in t
    int r = vm_idx[u] - N_REAL;
    int idx = r * VEC_PER_ROW + c;
    float4 acc = make_float4(0.f, 0.f, 0.f, 0.f);
#pragma unroll
    for (int k = 0; k < N_REP; k++) {
        float4 x = g_h2[k][idx];
        acc.x += x.x; acc.y += x.y; acc.z += x.z; acc.w += x.w;
    }
    float w = winv_of(r + N_REAL);
    acc.x *= w; acc.y *= w; acc.z *= w; acc.w *= w;
    out[t] = acc;                           // t == (u*8 + h)*16 + c
}

// ---------------------------------------------------------------------------
extern "C" void kernel_launch(void* const* d_in, const int* in_sizes, int n_in,
                              void* d_out, int out_size) {
    const float4* features   = (const float4*)d_in[0];  // [100000,64] f32
    const float4* virtue_emb = (const float4*)d_in[1];  // [2000,64]   f32
    const int*    cnodes     = (const int*)d_in[2];     // [30000] i32
    const int*    src        = (const int*)d_in[3];     // [512000] i32
    const int*    dst        = (const int*)d_in[4];     // [512000] i32
    const int*    vm_idx     = (const int*)d_in[5];     // [2000] i32
    float4*       out        = (float4*)d_out;          // [2000,8,64] f32

    void* p_z;
    cudaGetSymbolAddress(&p_z, g_z);
    cudaMemsetAsync(p_z, 0, sizeof(Zeroed), 0);

    k_prep   <<<PREP_INDEG_BLOCKS + PREP_H0_BLOCKS + PREP_ZERO1_BLOCKS +
                PREP_VPAIR_BLOCKS + PREP_ZERO2_BLOCKS, TB>>>(
                 features, virtue_emb, cnodes, src, dst);
    k_round1 <<<R1_BLOCKS, TB>>>(src, dst);
    k_round2e<<<R2_BLOCKS, TB>>>();
    k_bcast  <<<(BCAST_THREADS + TB - 1) / TB, TB>>>(vm_idx, out);
}